// round 2
// baseline (speedup 1.0000x reference)
#include <cuda_runtime.h>
#include <cuda_fp16.h>
#include <cstdint>

// ====================== device scratch (no allocs allowed) ======================
__device__ unsigned g_amax_bits;                       // bit pattern of max|W| (uint order == float order for nonneg)
// B fragments for mma.m16n8k16, precomputed in fragment layout:
// [kstep 0..255][ntile 0..7][lane 0..31] -> uint2 {b0, b1}
//   n = 8*ntile + (lane>>2)  (n<32: hi(A[n]), else lo(A[n-32]))
//   b0 = f16pair A'[n][16k + 2c, +1],  b1 = f16pair A'[n][16k+8 + 2c, +1],  c = lane&3
__device__ __align__(16) uint2 g_Bfrag[256 * 8 * 32];  // 512 KB

// ====================== constants ======================
static constexpr int K_DIM  = 4096;
static constexpr int N_OUT  = 12288;
static constexpr int M_OUT  = 32;
static constexpr int MTILE  = 64;                  // W rows per CTA (4 warps x 16)
static constexpr int KC     = 64;                  // k per chunk (4 ksteps of 16)
static constexpr int NCHUNK = K_DIM / KC;          // 64

#define SWZ(off) ((off) ^ (((off) >> 3) & 0x70))   // SW128 swizzle (128B rows)

// ====================== helpers ======================
static __device__ __forceinline__ uint32_t smem_u32(const void* p) {
    uint32_t a;
    asm("{ .reg .u64 t; cvta.to.shared.u64 t, %1; cvt.u32.u64 %0, t; }" : "=r"(a) : "l"(p));
    return a;
}

// quantize-dequant pair -> f16x2 of e4m3(RN-sat(w*scale)); lo half = a, hi half = b.
// Bit-exact vs reference: fp32 RN mul, RN-even saturating e4m3 cast, exact e4m3->f16.
static __device__ __forceinline__ uint32_t qd_pair(float a, float b, float scale) {
    float as = __fmul_rn(a, scale);
    float bs = __fmul_rn(b, scale);
    unsigned short p;
    asm("cvt.rn.satfinite.e4m3x2.f32 %0, %1, %2;" : "=h"(p) : "f"(bs), "f"(as));
    uint32_t r;
    asm("cvt.rn.f16x2.e4m3x2 %0, %1;" : "=r"(r) : "h"(p));
    return r;
}

static __device__ __forceinline__ void mma16816(float* d,
    uint32_t a0, uint32_t a1, uint32_t a2, uint32_t a3, uint32_t b0, uint32_t b1) {
    asm volatile(
        "mma.sync.aligned.m16n8k16.row.col.f32.f16.f16.f32 "
        "{%0,%1,%2,%3}, {%4,%5,%6,%7}, {%8,%9}, {%0,%1,%2,%3};"
        : "+f"(d[0]), "+f"(d[1]), "+f"(d[2]), "+f"(d[3])
        : "r"(a0), "r"(a1), "r"(a2), "r"(a3), "r"(b0), "r"(b1));
}

// ====================== kernel 1: build B fragments (A hi/lo split), reset amax ======================
__global__ void __launch_bounds__(256) k_prep(const float* __restrict__ A) {
    if (blockIdx.x == 0 && threadIdx.x == 0) g_amax_bits = 0u;
    const int idx   = blockIdx.x * 256 + threadIdx.x;   // 0..65535
    const int lane  = idx & 31;
    const int t     = (idx >> 5) & 7;
    const int kstep = idx >> 8;                          // 0..255
    const int n     = 8 * t + (lane >> 2);
    const int c     = lane & 3;
    const int K     = kstep * 16;
    const int r     = n & 31;
    const bool ishi = (n < 32);

    const float* Ar = A + (size_t)r * K_DIM;
    float2 p0 = *(const float2*)(Ar + K + 2 * c);
    float2 p1 = *(const float2*)(Ar + K + 8 + 2 * c);

    auto cv = [ishi](float x) -> uint32_t {
        __half h = __float2half_rn(x);
        if (!ishi) h = __float2half_rn(x - __half2float(h));   // lo residual
        return (uint32_t)__half_as_ushort(h);
    };
    uint32_t b0 = cv(p0.x) | (cv(p0.y) << 16);
    uint32_t b1 = cv(p1.x) | (cv(p1.y) << 16);
    g_Bfrag[idx] = make_uint2(b0, b1);
}

// ====================== kernel 2: amax over |W| ======================
__global__ void __launch_bounds__(256) k_amax(const float* __restrict__ W) {
    const float4* W4 = (const float4*)W;
    const int n4 = (N_OUT * K_DIM) / 4;
    float m0 = 0.f, m1 = 0.f, m2 = 0.f, m3 = 0.f;
    const int stride = gridDim.x * blockDim.x;
    for (int i = blockIdx.x * blockDim.x + threadIdx.x; i < n4; i += stride) {
        float4 v = W4[i];
        m0 = fmaxf(m0, fabsf(v.x));
        m1 = fmaxf(m1, fabsf(v.y));
        m2 = fmaxf(m2, fabsf(v.z));
        m3 = fmaxf(m3, fabsf(v.w));
    }
    float m = fmaxf(fmaxf(m0, m1), fmaxf(m2, m3));
    #pragma unroll
    for (int o = 16; o; o >>= 1) m = fmaxf(m, __shfl_xor_sync(0xFFFFFFFFu, m, o));
    if ((threadIdx.x & 31) == 0) atomicMax(&g_amax_bits, __float_as_uint(m));
}

// ====================== kernel 3: fused quantize + GEMM (mma.sync) ======================
// 192 CTAs x 128 threads. Each CTA: 64 W rows, full K. 4 warps x 16 rows.
__global__ void __launch_bounds__(128) k_gemm(const float* __restrict__ W,
                                              const float* __restrict__ bias,
                                              float* __restrict__ out) {
    __shared__ __align__(1024) char sbuf[2][MTILE * 128];  // 2 x 8KB, rows of 128B (64 f16 k)

    const int tid  = threadIdx.x;
    const int lane = tid & 31;
    const int wid  = tid >> 5;
    const int nb   = blockIdx.x * MTILE;

    const float amax  = fmaxf(__uint_as_float(g_amax_bits), 1e-12f);
    const float scale = __fdiv_rn(448.0f, amax);

    // producer mapping: 2 threads per row; each covers a 32-k half via 8x float4
    const int    row      = tid >> 1;                 // 0..63
    const int    khalf    = (tid & 1) * 32;           // 0 or 32
    const float* wrow     = W + (size_t)(nb + row) * K_DIM + khalf;
    const uint32_t sts_off = (uint32_t)(row * 128 + khalf * 2);

    // ldmatrix lane address (within-warp 16x16 A-fragment tiles)
    const int m    = lane >> 3;
    const int i8   = lane & 7;
    const uint32_t lm_off = (uint32_t)((wid * 16 + (m & 1) * 8 + i8) * 128 + (m >> 1) * 16);

    float acc[8][4];
    #pragma unroll
    for (int t = 0; t < 8; ++t)
        #pragma unroll
        for (int i = 0; i < 4; ++i) acc[t][i] = 0.f;

    float4 g[8];
    #pragma unroll
    for (int j = 0; j < 8; ++j) g[j] = *(const float4*)(wrow + 4 * j);

    for (int c = 0; c < NCHUNK; ++c) {
        __syncthreads();                                   // buf[c&1] free
        char* buf = sbuf[c & 1];
        #pragma unroll
        for (int j = 0; j < 8; ++j) {
            uint2 q = make_uint2(qd_pair(g[j].x, g[j].y, scale),
                                 qd_pair(g[j].z, g[j].w, scale));
            *(uint2*)(buf + SWZ(sts_off + 8 * j)) = q;
        }
        __syncthreads();                                   // tile visible

        if (c + 1 < NCHUNK) {                              // prefetch next chunk
            const float* wn = wrow + (c + 1) * KC;
            #pragma unroll
            for (int j = 0; j < 8; ++j) g[j] = *(const float4*)(wn + 4 * j);
        }

        const uint32_t bufb = smem_u32(buf);
        #pragma unroll
        for (int j = 0; j < 4; ++j) {                      // 4 ksteps of 16
            uint32_t a0, a1, a2, a3;
            uint32_t addr = bufb + SWZ(lm_off + 32 * j);
            asm volatile("ldmatrix.sync.aligned.m8n8.x4.shared.b16 {%0,%1,%2,%3}, [%4];"
                         : "=r"(a0), "=r"(a1), "=r"(a2), "=r"(a3) : "r"(addr));
            const uint2* bp = g_Bfrag + (size_t)((c * 4 + j) * 8) * 32 + lane;
            #pragma unroll
            for (int t = 0; t < 8; ++t) {
                uint2 b = __ldg(bp + t * 32);
                mma16816(acc[t], a0, a1, a2, a3, b.x, b.y);
            }
        }
    }

    // epilogue: combine hi(t) + lo(t+4), scale by recip, add bias
    const float recip = __frcp_rn(scale);
    const int g4  = lane >> 2;
    const int tig = lane & 3;
    const int w0  = nb + wid * 16 + g4;
    const int w1  = w0 + 8;
    const float b0 = bias[w0];
    const float b1 = bias[w1];
    #pragma unroll
    for (int t = 0; t < 4; ++t) {
        const int ar = 8 * t + 2 * tig;
        float v0 = (acc[t][0] + acc[t + 4][0]) * recip + b0;
        float v1 = (acc[t][1] + acc[t + 4][1]) * recip + b0;
        float v2 = (acc[t][2] + acc[t + 4][2]) * recip + b1;
        float v3 = (acc[t][3] + acc[t + 4][3]) * recip + b1;
        out[(size_t)ar * N_OUT + w0]       = v0;
        out[(size_t)(ar + 1) * N_OUT + w0] = v1;
        out[(size_t)ar * N_OUT + w1]       = v2;
        out[(size_t)(ar + 1) * N_OUT + w1] = v3;
    }
}

// ====================== launch ======================
extern "C" void kernel_launch(void* const* d_in, const int* in_sizes, int n_in,
                              void* d_out, int out_size) {
    const float* A    = (const float*)d_in[0];   // [32, 4096]
    const float* W    = (const float*)d_in[1];   // [12288, 4096]
    const float* bias = (const float*)d_in[2];   // [12288]
    float* out        = (float*)d_out;           // [32, 12288]

    k_prep<<<256, 256>>>(A);
    k_amax<<<1184, 256>>>(W);
    k_gemm<<<N_OUT / MTILE, 128>>>(W, bias, out);
}